// round 12
// baseline (speedup 1.0000x reference)
#include <cuda_runtime.h>
#include <cstdint>

#define BSZ 8192
#define DIM 768                     // int8: row = 768 bytes
#define BK 128                      // K bytes (=elems) per pipeline stage
#define NCH (DIM / BK)              // 6
#define SROW 144                    // padded smem row stride in bytes
#define TILE_B (128 * SROW)         // 18432 bytes per matrix per stage
#define STAGE_B (2 * TILE_B)
#define SMEM_TOTAL (2 * STAGE_B)    // 73728 bytes -> 2 CTAs/SM

// Static device scratch (no cudaMalloc allowed)
__device__ __align__(16) float g_rowsum[BSZ];
__device__ __align__(16) float g_colsum[BSZ];
__device__ __align__(16) float g_diag[BSZ];
__device__ __align__(16) float g_sa[BSZ];          // row scales for v
__device__ __align__(16) float g_sb[BSZ];          // row scales for u
__device__ __align__(16) int8_t g_vn[BSZ * DIM];   // int8 quantized v
__device__ __align__(16) int8_t g_un[BSZ * DIM];   // int8 quantized u

__device__ __forceinline__ uint32_t smem_u32(const void* p) {
    uint32_t a;
    asm("{ .reg .u64 t; cvta.to.shared.u64 t, %1; cvt.u32.u64 %0, t; }" : "=r"(a) : "l"(p));
    return a;
}
__device__ __forceinline__ void cp_async16(uint32_t dst, const void* src) {
    asm volatile("cp.async.cg.shared.global [%0], [%1], 16;" :: "r"(dst), "l"(src) : "memory");
}
__device__ __forceinline__ void cp_commit() {
    asm volatile("cp.async.commit_group;" ::: "memory");
}
template <int N>
__device__ __forceinline__ void cp_wait() {
    asm volatile("cp.async.wait_group %0;" :: "n"(N) : "memory");
}
__device__ __forceinline__ void ldmx4(uint32_t* r, uint32_t addr) {
    asm volatile("ldmatrix.sync.aligned.m8n8.x4.shared.b16 {%0,%1,%2,%3}, [%4];"
                 : "=r"(r[0]), "=r"(r[1]), "=r"(r[2]), "=r"(r[3]) : "r"(addr));
}
__device__ __forceinline__ void mma_s8(int32_t* d, const uint32_t* a,
                                       uint32_t b0, uint32_t b1) {
    asm volatile(
        "mma.sync.aligned.m16n8k32.row.col.s32.s8.s8.s32 "
        "{%0,%1,%2,%3}, {%4,%5,%6,%7}, {%8,%9}, {%0,%1,%2,%3};"
        : "+r"(d[0]), "+r"(d[1]), "+r"(d[2]), "+r"(d[3])
        : "r"(a[0]), "r"(a[1]), "r"(a[2]), "r"(a[3]), "r"(b0), "r"(b1));
}
// Pack 4 floats -> 4 saturated int8 in one u32 (byte0 = x0).
__device__ __forceinline__ uint32_t pack_s8x4(float x0, float x1, float x2, float x3,
                                              float s) {
    int q0 = __float2int_rn(x0 * s), q1 = __float2int_rn(x1 * s);
    int q2 = __float2int_rn(x2 * s), q3 = __float2int_rn(x3 * s);
    uint32_t t, r;
    asm("cvt.pack.sat.s8.s32.b32 %0, %1, %2, 0;"  : "=r"(t) : "r"(q3), "r"(q2));
    asm("cvt.pack.sat.s8.s32.b32 %0, %1, %2, %3;" : "=r"(r) : "r"(q1), "r"(q0), "r"(t));
    return r;
}

// ---------------------------------------------------------------------------
// Kernel 1: warp-per-row normalize (barrier-free) -> per-row-scaled int8.
// q = round(127*x / max|x_row|); scale sA = max|x_row| / (127*norm) so that
// cos = dot_int * sA_i * sB_j. Exact fp32 diag; zero accumulators + out.
// ---------------------------------------------------------------------------
__global__ void normalize_kernel(const float* __restrict__ v,
                                 const float* __restrict__ u,
                                 float* __restrict__ out) {
    const int row = blockIdx.x * 8 + (threadIdx.x >> 5);
    const int lane = threadIdx.x & 31;
    if (lane == 0) {
        g_rowsum[row] = 0.0f;
        g_colsum[row] = 0.0f;
        if (row == 0) out[0] = 0.0f;
    }
    const float4* vr = (const float4*)(v + (size_t)row * DIM);
    const float4* ur = (const float4*)(u + (size_t)row * DIM);

    float4 a[6], b[6];
    float sv = 0.f, su = 0.f, dp = 0.f, mv = 0.f, mu = 0.f;
    #pragma unroll
    for (int i = 0; i < 6; i++) {
        a[i] = vr[lane + 32 * i];
        b[i] = ur[lane + 32 * i];
        sv += a[i].x * a[i].x + a[i].y * a[i].y + a[i].z * a[i].z + a[i].w * a[i].w;
        su += b[i].x * b[i].x + b[i].y * b[i].y + b[i].z * b[i].z + b[i].w * b[i].w;
        dp += a[i].x * b[i].x + a[i].y * b[i].y + a[i].z * b[i].z + a[i].w * b[i].w;
        mv = fmaxf(mv, fmaxf(fmaxf(fabsf(a[i].x), fabsf(a[i].y)),
                             fmaxf(fabsf(a[i].z), fabsf(a[i].w))));
        mu = fmaxf(mu, fmaxf(fmaxf(fabsf(b[i].x), fabsf(b[i].y)),
                             fmaxf(fabsf(b[i].z), fabsf(b[i].w))));
    }
    #pragma unroll
    for (int o = 16; o > 0; o >>= 1) {
        sv += __shfl_xor_sync(0xFFFFFFFFu, sv, o);
        su += __shfl_xor_sync(0xFFFFFFFFu, su, o);
        dp += __shfl_xor_sync(0xFFFFFFFFu, dp, o);
        mv = fmaxf(mv, __shfl_xor_sync(0xFFFFFFFFu, mv, o));
        mu = fmaxf(mu, __shfl_xor_sync(0xFFFFFFFFu, mu, o));
    }
    const float nv = fmaxf(sqrtf(sv), 1e-8f);
    const float nu = fmaxf(sqrtf(su), 1e-8f);
    mv = fmaxf(mv, 1e-20f);
    mu = fmaxf(mu, 1e-20f);
    if (lane == 0) {
        g_diag[row] = dp / (nv * nu);
        g_sa[row] = mv / (127.0f * nv);
        g_sb[row] = mu / (127.0f * nu);
    }
    const float qv = 127.0f / mv, qu = 127.0f / mu;

    uint32_t* dv = (uint32_t*)(g_vn + (size_t)row * DIM);
    uint32_t* du = (uint32_t*)(g_un + (size_t)row * DIM);
    #pragma unroll
    for (int i = 0; i < 6; i++) {
        dv[lane + 32 * i] = pack_s8x4(a[i].x, a[i].y, a[i].z, a[i].w, qv);
        du[lane + 32 * i] = pack_s8x4(b[i].x, b[i].y, b[i].z, b[i].w, qu);
    }
}

// ---------------------------------------------------------------------------
// Kernel 2: 128x128 tile INT8 IMMA GEMM, K=768 (6 chunks of 128B), cp.async
// double-buffered with the round-11 single-sync loop, ldmatrix fragments
// (byte-identical addressing to the verified fp8 k32 kernel), fused
// exp(10*cos-10) + row/col sum epilogue with per-row/col dequant scales.
// ---------------------------------------------------------------------------
__global__ __launch_bounds__(256, 2) void gemm_lse_kernel() {
    extern __shared__ char smem[];
    __shared__ float s_row[128];
    __shared__ float s_col[128];
    __shared__ float s_sa[128];
    __shared__ float s_sb[128];
    const uint32_t sb = smem_u32(smem);

    const int tid = threadIdx.x;
    const int warp = tid >> 5, lane = tid & 31;
    const int m0 = blockIdx.y * 128, n0 = blockIdx.x * 128;

    if (tid < 128) {
        s_row[tid] = 0.0f;
        s_col[tid] = 0.0f;
        s_sa[tid] = g_sa[m0 + tid];
        s_sb[tid] = g_sb[n0 + tid];
    }

    const int wm = warp >> 2;        // 0..1 (64-row slab)
    const int wn = warp & 3;         // 0..3 (32-col slab)
    const int gID = lane >> 2;       // 0..7
    const int tid4 = lane & 3;       // 0..3

    const int ldr = tid >> 3;        // 0..31 base row
    const int ldg = (tid & 7) * 16;  // 16B granule in 128B of K-data

    const int aRow = lane & 15, aSel = (lane >> 4) * 16;
    const int bRow = lane & 7,  bSel = (lane >> 3) * 16;

    int32_t acc[4][4][4];
    #pragma unroll
    for (int mt = 0; mt < 4; mt++)
        #pragma unroll
        for (int nt = 0; nt < 4; nt++)
            #pragma unroll
            for (int i = 0; i < 4; i++) acc[mt][nt][i] = 0;

    auto load_tile = [&](int c, int buf) {
        const uint32_t dA = sb + buf * STAGE_B;
        const uint32_t dB = dA + TILE_B;
        const size_t koff = (size_t)c * BK;   // bytes along a 768B row
        #pragma unroll
        for (int p = 0; p < 4; p++) {
            const int row = ldr + p * 32;
            cp_async16(dA + row * SROW + ldg,
                       g_vn + (size_t)(m0 + row) * DIM + koff + ldg);
            cp_async16(dB + row * SROW + ldg,
                       g_un + (size_t)(n0 + row) * DIM + koff + ldg);
        }
        cp_commit();
    };

    load_tile(0, 0);

    for (int c = 0; c < NCH; c++) {
        const int buf = c & 1;
        cp_wait<0>();        // group(c) is the only one outstanding -> landed
        __syncthreads();     // all warps done computing c-1; all see stage c
        if (c + 1 < NCH) load_tile(c + 1, buf ^ 1);   // overwrites (c-1) slot

        const uint32_t bA = sb + buf * STAGE_B;
        const uint32_t bB = bA + TILE_B;
        #pragma unroll
        for (int kp = 0; kp < 2; kp++) {        // two 64-byte halves
            const int kb = kp * 64;
            uint32_t bfr[4][4];                 // [nt][2 ksteps x {b0,b1}]
            #pragma unroll
            for (int nt = 0; nt < 4; nt++)
                ldmx4(bfr[nt], bB + (wn * 32 + nt * 8 + bRow) * SROW + kb + bSel);
            #pragma unroll
            for (int ks = 0; ks < 2; ks++) {    // k32 steps within half
                uint32_t af[4][4];
                #pragma unroll
                for (int mt = 0; mt < 4; mt++)
                    ldmx4(af[mt], bA + (wm * 64 + mt * 16 + aRow) * SROW + kb + ks * 32 + aSel);
                #pragma unroll
                for (int mt = 0; mt < 4; mt++)
                    #pragma unroll
                    for (int nt = 0; nt < 4; nt++)
                        mma_s8(acc[mt][nt], af[mt], bfr[nt][ks * 2], bfr[nt][ks * 2 + 1]);
            }
        }
    }
    __syncthreads();   // mainloop done; s_sa/s_sb (written pre-loop) valid

    // Epilogue: cos = dot_int*sA*sB; e = exp(10*cos-10); row/col partials.
    float sa0[4], sa1[4], sb0[4], sb1[4];
    #pragma unroll
    for (int mt = 0; mt < 4; mt++) {
        sa0[mt] = s_sa[wm * 64 + mt * 16 + gID];
        sa1[mt] = s_sa[wm * 64 + mt * 16 + gID + 8];
    }
    #pragma unroll
    for (int nt = 0; nt < 4; nt++) {
        sb0[nt] = s_sb[wn * 32 + nt * 8 + tid4 * 2];
        sb1[nt] = s_sb[wn * 32 + nt * 8 + tid4 * 2 + 1];
    }
    float rs0[4] = {0.f, 0.f, 0.f, 0.f};
    float rs1[4] = {0.f, 0.f, 0.f, 0.f};
    float ce[4]  = {0.f, 0.f, 0.f, 0.f};
    float co[4]  = {0.f, 0.f, 0.f, 0.f};
    #pragma unroll
    for (int mt = 0; mt < 4; mt++) {
        #pragma unroll
        for (int nt = 0; nt < 4; nt++) {
            float c0 = (float)acc[mt][nt][0] * (sa0[mt] * sb0[nt]);
            float c1 = (float)acc[mt][nt][1] * (sa0[mt] * sb1[nt]);
            float c2 = (float)acc[mt][nt][2] * (sa1[mt] * sb0[nt]);
            float c3 = (float)acc[mt][nt][3] * (sa1[mt] * sb1[nt]);
            float e0 = __expf(fmaf(c0, 10.0f, -10.0f));
            float e1 = __expf(fmaf(c1, 10.0f, -10.0f));
            float e2 = __expf(fmaf(c2, 10.0f, -10.0f));
            float e3 = __expf(fmaf(c3, 10.0f, -10.0f));
            rs0[mt] += e0 + e1;
            rs1[mt] += e2 + e3;
            ce[nt]  += e0 + e2;
            co[nt]  += e1 + e3;
        }
    }
    #pragma unroll
    for (int mt = 0; mt < 4; mt++) {
        float v0 = rs0[mt], v1 = rs1[mt];
        v0 += __shfl_xor_sync(0xFFFFFFFFu, v0, 1);
        v0 += __shfl_xor_sync(0xFFFFFFFFu, v0, 2);
        v1 += __shfl_xor_sync(0xFFFFFFFFu, v1, 1);
        v1 += __shfl_xor_sync(0xFFFFFFFFu, v1, 2);
        if (tid4 == 0) {
            atomicAdd(&s_row[wm * 64 + mt * 16 + gID], v0);
            atomicAdd(&s_row[wm * 64 + mt * 16 + gID + 8], v1);
        }
    }
    #pragma unroll
    for (int nt = 0; nt < 4; nt++) {
        float a = ce[nt], b = co[nt];
        a += __shfl_xor_sync(0xFFFFFFFFu, a, 4);
        a += __shfl_xor_sync(0xFFFFFFFFu, a, 8);
        a += __shfl_xor_sync(0xFFFFFFFFu, a, 16);
        b += __shfl_xor_sync(0xFFFFFFFFu, b, 4);
        b += __shfl_xor_sync(0xFFFFFFFFu, b, 8);
        b += __shfl_xor_sync(0xFFFFFFFFu, b, 16);
        if (lane < 4) {
            atomicAdd(&s_col[wn * 32 + nt * 8 + lane * 2], a);
            atomicAdd(&s_col[wn * 32 + nt * 8 + lane * 2 + 1], b);
        }
    }
    __syncthreads();
    if (tid < 128)       atomicAdd(&g_rowsum[m0 + tid], s_row[tid]);
    else                 atomicAdd(&g_colsum[n0 + tid - 128], s_col[tid - 128]);
}

// ---------------------------------------------------------------------------
// Kernel 3: finalize -> atomic accumulate of block partials into out[0]
// (out zeroed by normalize_kernel; same-stream ordering guarantees it).
// ---------------------------------------------------------------------------
__global__ void fin_kernel(float* __restrict__ out) {
    int i = blockIdx.x * 256 + threadIdx.x;
    float d10 = g_diag[i] * 10.0f;
    float li = logf(g_rowsum[i]) + 10.0f - d10;
    float lt = logf(g_colsum[i]) + 10.0f - d10;
    float s = 0.75f * li + 0.25f * lt;
    #pragma unroll
    for (int o = 16; o > 0; o >>= 1) s += __shfl_xor_sync(0xFFFFFFFFu, s, o);
    __shared__ float sh[8];
    int w = threadIdx.x >> 5, l = threadIdx.x & 31;
    if (l == 0) sh[w] = s;
    __syncthreads();
    if (threadIdx.x == 0) {
        float t = 0.f;
        #pragma unroll
        for (int i2 = 0; i2 < 8; i2++) t += sh[i2];
        atomicAdd(out, t * (1.0f / BSZ));
    }
}

extern "C" void kernel_launch(void* const* d_in, const int* in_sizes, int n_in,
                              void* d_out, int out_size) {
    const float* v = (const float*)d_in[0];
    const float* u = (const float*)d_in[1];
    float* out = (float*)d_out;

    static bool attr_set = false;
    if (!attr_set) {
        cudaFuncSetAttribute(gemm_lse_kernel,
                             cudaFuncAttributeMaxDynamicSharedMemorySize, SMEM_TOTAL);
        attr_set = true;
    }

    normalize_kernel<<<BSZ / 8, 256>>>(v, u, out);
    gemm_lse_kernel<<<dim3(64, 64), 256, SMEM_TOTAL>>>();
    fin_kernel<<<32, 256>>>(out);
}

// round 13
// speedup vs baseline: 2.5456x; 2.5456x over previous
#include <cuda_runtime.h>
#include <cuda_bf16.h>
#include <cstdint>

#define BSZ 8192
#define DIM 768
#define BK 64                       // K elems per pipeline stage (bf16)
#define NCH (DIM / BK)              // 12
#define SROW 144                    // padded smem row stride in bytes
#define TILE_B (128 * SROW)         // 18432 bytes per tile
#define OFF_A 0
#define OFF_B (2 * TILE_B)
#define SMEM_TOTAL (4 * TILE_B)     // 73728 bytes -> 2 CTAs/SM

// Static device scratch (no cudaMalloc allowed)
__device__ __align__(16) float g_rowsum[BSZ];
__device__ __align__(16) float g_colsum[BSZ];
__device__ __align__(16) float g_diag[BSZ];
__device__ __align__(16) __nv_bfloat16 g_vn[BSZ * DIM];
__device__ __align__(16) __nv_bfloat16 g_un[BSZ * DIM];

__device__ __forceinline__ uint32_t smem_u32(const void* p) {
    uint32_t a;
    asm("{ .reg .u64 t; cvta.to.shared.u64 t, %1; cvt.u32.u64 %0, t; }" : "=r"(a) : "l"(p));
    return a;
}
__device__ __forceinline__ void cp_async16(uint32_t dst, const void* src) {
    asm volatile("cp.async.cg.shared.global [%0], [%1], 16;" :: "r"(dst), "l"(src) : "memory");
}
__device__ __forceinline__ void cp_commit() {
    asm volatile("cp.async.commit_group;" ::: "memory");
}
template <int N>
__device__ __forceinline__ void cp_wait() {
    asm volatile("cp.async.wait_group %0;" :: "n"(N) : "memory");
}
__device__ __forceinline__ void ldmx4(uint32_t* r, uint32_t addr) {
    asm volatile("ldmatrix.sync.aligned.m8n8.x4.shared.b16 {%0,%1,%2,%3}, [%4];"
                 : "=r"(r[0]), "=r"(r[1]), "=r"(r[2]), "=r"(r[3]) : "r"(addr));
}
__device__ __forceinline__ void mma16816(float* d, const uint32_t* a, uint32_t b0, uint32_t b1) {
    asm volatile(
        "mma.sync.aligned.m16n8k16.row.col.f32.bf16.bf16.f32 "
        "{%0,%1,%2,%3}, {%4,%5,%6,%7}, {%8,%9}, {%0,%1,%2,%3};"
        : "+f"(d[0]), "+f"(d[1]), "+f"(d[2]), "+f"(d[3])
        : "r"(a[0]), "r"(a[1]), "r"(a[2]), "r"(a[3]), "r"(b0), "r"(b1));
}

// ---------------------------------------------------------------------------
// Kernel 1: warp-per-row normalize (barrier-free). Butterfly reductions give
// every lane identical fp32 sums; exact fp32 diag; zero accumulators + out.
// ---------------------------------------------------------------------------
__global__ void normalize_kernel(const float* __restrict__ v,
                                 const float* __restrict__ u,
                                 float* __restrict__ out) {
    const int row = blockIdx.x * 8 + (threadIdx.x >> 5);
    const int lane = threadIdx.x & 31;
    if (lane == 0) {
        g_rowsum[row] = 0.0f;
        g_colsum[row] = 0.0f;
        if (row == 0) out[0] = 0.0f;
    }
    const float4* vr = (const float4*)(v + (size_t)row * DIM);
    const float4* ur = (const float4*)(u + (size_t)row * DIM);

    float4 a[6], b[6];
    float sv = 0.f, su = 0.f, dp = 0.f;
    #pragma unroll
    for (int i = 0; i < 6; i++) {
        a[i] = vr[lane + 32 * i];
        b[i] = ur[lane + 32 * i];
        sv += a[i].x * a[i].x + a[i].y * a[i].y + a[i].z * a[i].z + a[i].w * a[i].w;
        su += b[i].x * b[i].x + b[i].y * b[i].y + b[i].z * b[i].z + b[i].w * b[i].w;
        dp += a[i].x * b[i].x + a[i].y * b[i].y + a[i].z * b[i].z + a[i].w * b[i].w;
    }
    #pragma unroll
    for (int o = 16; o > 0; o >>= 1) {
        sv += __shfl_xor_sync(0xFFFFFFFFu, sv, o);
        su += __shfl_xor_sync(0xFFFFFFFFu, su, o);
        dp += __shfl_xor_sync(0xFFFFFFFFu, dp, o);
    }
    const float nv = fmaxf(sqrtf(sv), 1e-8f);
    const float nu = fmaxf(sqrtf(su), 1e-8f);
    if (lane == 0) g_diag[row] = dp / (nv * nu);
    const float iv = 1.0f / nv, iu = 1.0f / nu;

    uint2* dv = (uint2*)(g_vn + (size_t)row * DIM);
    uint2* du = (uint2*)(g_un + (size_t)row * DIM);
    #pragma unroll
    for (int i = 0; i < 6; i++) {
        __nv_bfloat162 p0 = {__float2bfloat16(a[i].x * iv), __float2bfloat16(a[i].y * iv)};
        __nv_bfloat162 p1 = {__float2bfloat16(a[i].z * iv), __float2bfloat16(a[i].w * iv)};
        __nv_bfloat162 q0 = {__float2bfloat16(b[i].x * iu), __float2bfloat16(b[i].y * iu)};
        __nv_bfloat162 q1 = {__float2bfloat16(b[i].z * iu), __float2bfloat16(b[i].w * iu)};
        dv[lane + 32 * i] = make_uint2(*(uint32_t*)&p0, *(uint32_t*)&p1);
        du[lane + 32 * i] = make_uint2(*(uint32_t*)&q0, *(uint32_t*)&q1);
    }
}

// ---------------------------------------------------------------------------
// Kernel 2: 128x128 tile bf16 mma.sync GEMM, K=768, cp.async double-buffered,
// single barrier per chunk. Prefetch for chunk c+1 is issued BETWEEN the two
// half-chunk compute blocks so the LDGSTS burst is absorbed while the tensor
// pipe is busy, instead of delaying the first ldmatrix batch.
// Fused exp(10*cos-10) + row/col sum epilogue.
// ---------------------------------------------------------------------------
__global__ __launch_bounds__(256, 2) void gemm_lse_kernel() {
    extern __shared__ char smem[];
    __shared__ float s_row[128];
    __shared__ float s_col[128];
    const uint32_t sb = smem_u32(smem);

    const int tid = threadIdx.x;
    const int warp = tid >> 5, lane = tid & 31;
    const int m0 = blockIdx.y * 128, n0 = blockIdx.x * 128;

    if (tid < 128) { s_row[tid] = 0.0f; s_col[tid] = 0.0f; }

    const int wm = warp >> 2;        // 0..1 (64-row slab)
    const int wn = warp & 3;         // 0..3 (32-col slab)
    const int gID = lane >> 2;       // 0..7
    const int tid4 = lane & 3;       // 0..3

    const int ldr = tid >> 3;        // 0..31 base row
    const int ldg = (tid & 7) * 16;  // 16B granule in 128B of K-data

    const int aRow = lane & 15, aSel = (lane >> 4) * 16;
    const int bRow = lane & 7,  bSel = (lane >> 3) * 16;

    float acc[4][4][4];
    #pragma unroll
    for (int mt = 0; mt < 4; mt++)
        #pragma unroll
        for (int nt = 0; nt < 4; nt++)
            #pragma unroll
            for (int i = 0; i < 4; i++) acc[mt][nt][i] = 0.0f;

    auto load_tile = [&](int c, int buf) {
        const uint32_t dA = sb + OFF_A + buf * TILE_B;
        const uint32_t dB = sb + OFF_B + buf * TILE_B;
        const size_t koff = (size_t)c * BK * 2;   // bytes along row
        #pragma unroll
        for (int p = 0; p < 4; p++) {
            const int row = ldr + p * 32;
            cp_async16(dA + row * SROW + ldg,
                       (const char*)g_vn + ((size_t)(m0 + row) * DIM) * 2 + koff + ldg);
            cp_async16(dB + row * SROW + ldg,
                       (const char*)g_un + ((size_t)(n0 + row) * DIM) * 2 + koff + ldg);
        }
        cp_commit();
    };

    load_tile(0, 0);

    for (int c = 0; c < NCH; c++) {
        const int buf = c & 1;
        cp_wait<0>();        // group(c) is the only one outstanding -> landed
        __syncthreads();     // all warps done computing c-1; all see stage c

        const uint32_t bA = sb + OFF_A + buf * TILE_B;
        const uint32_t bB = sb + OFF_B + buf * TILE_B;

        // -- half-chunk kp = 0: compute first (tensor pipe starts at once) --
        {
            uint32_t bfr[4][4];
            #pragma unroll
            for (int nt = 0; nt < 4; nt++)
                ldmx4(bfr[nt], bB + (wn * 32 + nt * 8 + bRow) * SROW + bSel);
            #pragma unroll
            for (int ks = 0; ks < 2; ks++) {
                const int kc = ks * 16;
                uint32_t af[4][4];
                #pragma unroll
                for (int mt = 0; mt < 4; mt++)
                    ldmx4(af[mt], bA + (wm * 64 + mt * 16 + aRow) * SROW + kc * 2 + aSel);
                #pragma unroll
                for (int mt = 0; mt < 4; mt++)
                    #pragma unroll
                    for (int nt = 0; nt < 4; nt++)
                        mma16816(acc[mt][nt], af[mt], bfr[nt][ks * 2], bfr[nt][ks * 2 + 1]);
            }
        }

        // -- prefetch c+1 now: LDGSTS burst hides under kp=0/kp=1 compute --
        if (c + 1 < NCH) load_tile(c + 1, buf ^ 1);   // overwrites (c-1) slot

        // -- half-chunk kp = 1 --
        {
            const int kk = 32;
            uint32_t bfr[4][4];
            #pragma unroll
            for (int nt = 0; nt < 4; nt++)
                ldmx4(bfr[nt], bB + (wn * 32 + nt * 8 + bRow) * SROW + kk * 2 + bSel);
            #pragma unroll
            for (int ks = 0; ks < 2; ks++) {
                const int kc = kk + ks * 16;
                uint32_t af[4][4];
                #pragma unroll
                for (int mt = 0; mt < 4; mt++)
                    ldmx4(af[mt], bA + (wm * 64 + mt * 16 + aRow) * SROW + kc * 2 + aSel);
                #pragma unroll
                for (int mt = 0; mt < 4; mt++)
                    #pragma unroll
                    for (int nt = 0; nt < 4; nt++)
                        mma16816(acc[mt][nt], af[mt], bfr[nt][ks * 2], bfr[nt][ks * 2 + 1]);
            }
        }
    }

    // Epilogue: e = exp(cos*10 - 10); per-row / per-col partial sums.
    float rs0[4] = {0.f, 0.f, 0.f, 0.f};
    float rs1[4] = {0.f, 0.f, 0.f, 0.f};
    float ce[4]  = {0.f, 0.f, 0.f, 0.f};
    float co[4]  = {0.f, 0.f, 0.f, 0.f};
    #pragma unroll
    for (int mt = 0; mt < 4; mt++) {
        #pragma unroll
        for (int nt = 0; nt < 4; nt++) {
            float e0 = __expf(fmaf(acc[mt][nt][0], 10.0f, -10.0f));
            float e1 = __expf(fmaf(acc[mt][nt][1], 10.0f, -10.0f));
            float e2 = __expf(fmaf(acc[mt][nt][2], 10.0f, -10.0f));
            float e3 = __expf(fmaf(acc[mt][nt][3], 10.0f, -10.0f));
            rs0[mt] += e0 + e1;
            rs1[mt] += e2 + e3;
            ce[nt]  += e0 + e2;
            co[nt]  += e1 + e3;
        }
    }
    #pragma unroll
    for (int mt = 0; mt < 4; mt++) {
        float v0 = rs0[mt], v1 = rs1[mt];
        v0 += __shfl_xor_sync(0xFFFFFFFFu, v0, 1);
        v0 += __shfl_xor_sync(0xFFFFFFFFu, v0, 2);
        v1 += __shfl_xor_sync(0xFFFFFFFFu, v1, 1);
        v1 += __shfl_xor_sync(0xFFFFFFFFu, v1, 2);
        if (tid4 == 0) {
            atomicAdd(&s_row[wm * 64 + mt * 16 + gID], v0);
            atomicAdd(&s_row[wm * 64 + mt * 16 + gID + 8], v1);
        }
    }
    #pragma unroll
    for (int nt = 0; nt < 4; nt++) {
        float a = ce[nt], b = co[nt];
        a += __shfl_xor_sync(0xFFFFFFFFu, a, 4);
        a += __shfl_xor_sync(0xFFFFFFFFu, a, 8);
        a += __shfl_xor_sync(0xFFFFFFFFu, a, 16);
        b += __shfl_xor_sync(0xFFFFFFFFu, b, 4);
        b += __shfl_xor_sync(0xFFFFFFFFu, b, 8);
        b += __shfl_xor_sync(0xFFFFFFFFu, b, 16);
        if (lane < 4) {
            atomicAdd(&s_col[wn * 32 + nt * 8 + lane * 2], a);
            atomicAdd(&s_col[wn * 32 + nt * 8 + lane * 2 + 1], b);
        }
    }
    __syncthreads();
    if (tid < 128)       atomicAdd(&g_rowsum[m0 + tid], s_row[tid]);
    else                 atomicAdd(&g_colsum[n0 + tid - 128], s_col[tid - 128]);
}

// ---------------------------------------------------------------------------
// Kernel 3: finalize -> atomic accumulate of block partials into out[0]
// (out zeroed by normalize_kernel; same-stream ordering guarantees it).
// ---------------------------------------------------------------------------
__global__ void fin_kernel(float* __restrict__ out) {
    int i = blockIdx.x * 256 + threadIdx.x;
    float d10 = g_diag[i] * 10.0f;
    float li = logf(g_rowsum[i]) + 10.0f - d10;
    float lt = logf(g_colsum[i]) + 10.0f - d10;
    float s = 0.75f * li + 0.25f * lt;
    #pragma unroll
    for (int o = 16; o > 0; o >>= 1) s += __shfl_xor_sync(0xFFFFFFFFu, s, o);
    __shared__ float sh[8];
    int w = threadIdx.x >> 5, l = threadIdx.x & 31;
    if (l == 0) sh[w] = s;
    __syncthreads();
    if (threadIdx.x == 0) {
        float t = 0.f;
        #pragma unroll
        for (int i2 = 0; i2 < 8; i2++) t += sh[i2];
        atomicAdd(out, t * (1.0f / BSZ));
    }
}

extern "C" void kernel_launch(void* const* d_in, const int* in_sizes, int n_in,
                              void* d_out, int out_size) {
    const float* v = (const float*)d_in[0];
    const float* u = (const float*)d_in[1];
    float* out = (float*)d_out;

    static bool attr_set = false;
    if (!attr_set) {
        cudaFuncSetAttribute(gemm_lse_kernel,
                             cudaFuncAttributeMaxDynamicSharedMemorySize, SMEM_TOTAL);
        attr_set = true;
    }

    normalize_kernel<<<BSZ / 8, 256>>>(v, u, out);
    gemm_lse_kernel<<<dim3(64, 64), 256, SMEM_TOTAL>>>();
    fin_kernel<<<32, 256>>>(out);
}

// round 15
// speedup vs baseline: 2.7129x; 1.0657x over previous
#include <cuda_runtime.h>
#include <cuda_bf16.h>
#include <cstdint>

#define BSZ 8192
#define DIM 768
#define BK 64                       // K elems per pipeline stage (bf16)
#define NCH (DIM / BK)              // 12
#define SROW 144                    // padded smem row stride in bytes
#define TILE_B (128 * SROW)         // 18432 bytes per tile
#define OFF_A 0
#define OFF_B (2 * TILE_B)
#define SMEM_TOTAL (4 * TILE_B)     // 73728 bytes -> 2 CTAs/SM

// Static device scratch (no cudaMalloc allowed)
__device__ __align__(16) float g_rowsum[BSZ];
__device__ __align__(16) float g_colsum[BSZ];
__device__ __align__(16) float g_diag[BSZ];
__device__ __align__(16) __nv_bfloat16 g_vn[BSZ * DIM];
__device__ __align__(16) __nv_bfloat16 g_un[BSZ * DIM];

__device__ __forceinline__ uint32_t smem_u32(const void* p) {
    uint32_t a;
    asm("{ .reg .u64 t; cvta.to.shared.u64 t, %1; cvt.u32.u64 %0, t; }" : "=r"(a) : "l"(p));
    return a;
}
__device__ __forceinline__ void cp_async16(uint32_t dst, const void* src) {
    asm volatile("cp.async.cg.shared.global [%0], [%1], 16;" :: "r"(dst), "l"(src) : "memory");
}
__device__ __forceinline__ void cp_commit() {
    asm volatile("cp.async.commit_group;" ::: "memory");
}
template <int N>
__device__ __forceinline__ void cp_wait() {
    asm volatile("cp.async.wait_group %0;" :: "n"(N) : "memory");
}
__device__ __forceinline__ void ldmx4(uint32_t* r, uint32_t addr) {
    asm volatile("ldmatrix.sync.aligned.m8n8.x4.shared.b16 {%0,%1,%2,%3}, [%4];"
                 : "=r"(r[0]), "=r"(r[1]), "=r"(r[2]), "=r"(r[3]) : "r"(addr));
}
__device__ __forceinline__ void mma16816(float* d, const uint32_t* a, uint32_t b0, uint32_t b1) {
    asm volatile(
        "mma.sync.aligned.m16n8k16.row.col.f32.bf16.bf16.f32 "
        "{%0,%1,%2,%3}, {%4,%5,%6,%7}, {%8,%9}, {%0,%1,%2,%3};"
        : "+f"(d[0]), "+f"(d[1]), "+f"(d[2]), "+f"(d[3])
        : "r"(a[0]), "r"(a[1]), "r"(a[2]), "r"(a[3]), "r"(b0), "r"(b1));
}

// ---------------------------------------------------------------------------
// Kernel 1: warp-per-row normalize (barrier-free). Butterfly reductions give
// every lane identical fp32 sums; exact fp32 diag; zero accumulators + out.
// ---------------------------------------------------------------------------
__global__ void normalize_kernel(const float* __restrict__ v,
                                 const float* __restrict__ u,
                                 float* __restrict__ out) {
    const int row = blockIdx.x * 8 + (threadIdx.x >> 5);
    const int lane = threadIdx.x & 31;
    if (lane == 0) {
        g_rowsum[row] = 0.0f;
        g_colsum[row] = 0.0f;
        if (row == 0) out[0] = 0.0f;
    }
    const float4* vr = (const float4*)(v + (size_t)row * DIM);
    const float4* ur = (const float4*)(u + (size_t)row * DIM);

    float4 a[6], b[6];
    float sv = 0.f, su = 0.f, dp = 0.f;
    #pragma unroll
    for (int i = 0; i < 6; i++) {
        a[i] = vr[lane + 32 * i];
        b[i] = ur[lane + 32 * i];
        sv += a[i].x * a[i].x + a[i].y * a[i].y + a[i].z * a[i].z + a[i].w * a[i].w;
        su += b[i].x * b[i].x + b[i].y * b[i].y + b[i].z * b[i].z + b[i].w * b[i].w;
        dp += a[i].x * b[i].x + a[i].y * b[i].y + a[i].z * b[i].z + a[i].w * b[i].w;
    }
    #pragma unroll
    for (int o = 16; o > 0; o >>= 1) {
        sv += __shfl_xor_sync(0xFFFFFFFFu, sv, o);
        su += __shfl_xor_sync(0xFFFFFFFFu, su, o);
        dp += __shfl_xor_sync(0xFFFFFFFFu, dp, o);
    }
    const float nv = fmaxf(sqrtf(sv), 1e-8f);
    const float nu = fmaxf(sqrtf(su), 1e-8f);
    if (lane == 0) g_diag[row] = dp / (nv * nu);
    const float iv = 1.0f / nv, iu = 1.0f / nu;

    uint2* dv = (uint2*)(g_vn + (size_t)row * DIM);
    uint2* du = (uint2*)(g_un + (size_t)row * DIM);
    #pragma unroll
    for (int i = 0; i < 6; i++) {
        __nv_bfloat162 p0 = {__float2bfloat16(a[i].x * iv), __float2bfloat16(a[i].y * iv)};
        __nv_bfloat162 p1 = {__float2bfloat16(a[i].z * iv), __float2bfloat16(a[i].w * iv)};
        __nv_bfloat162 q0 = {__float2bfloat16(b[i].x * iu), __float2bfloat16(b[i].y * iu)};
        __nv_bfloat162 q1 = {__float2bfloat16(b[i].z * iu), __float2bfloat16(b[i].w * iu)};
        dv[lane + 32 * i] = make_uint2(*(uint32_t*)&p0, *(uint32_t*)&p1);
        du[lane + 32 * i] = make_uint2(*(uint32_t*)&q0, *(uint32_t*)&q1);
    }
}

// ---------------------------------------------------------------------------
// Kernel 2: 128x128 tile bf16 mma.sync GEMM, K=768, cp.async double-buffered,
// single barrier per chunk. Prefetch for chunk c+1 is split 4+4 and sunk INTO
// the MMA shadow (right after a 16-MMA block, where the warp stalls on tensor
// dispatch and the LSU has no LDSMs in flight), so no LDGSTS burst ever sits
// in front of a fragment-load batch. Fused exp(10*cos-10) + row/col epilogue.
// ---------------------------------------------------------------------------
__global__ __launch_bounds__(256, 2) void gemm_lse_kernel() {
    extern __shared__ char smem[];
    __shared__ float s_row[128];
    __shared__ float s_col[128];
    const uint32_t sb = smem_u32(smem);

    const int tid = threadIdx.x;
    const int warp = tid >> 5, lane = tid & 31;
    const int m0 = blockIdx.y * 128, n0 = blockIdx.x * 128;

    if (tid < 128) { s_row[tid] = 0.0f; s_col[tid] = 0.0f; }

    const int wm = warp >> 2;        // 0..1 (64-row slab)
    const int wn = warp & 3;         // 0..3 (32-col slab)
    const int gID = lane >> 2;       // 0..7
    const int tid4 = lane & 3;       // 0..3

    const int ldr = tid >> 3;        // 0..31 base row
    const int ldg = (tid & 7) * 16;  // 16B granule in 128B of K-data

    const int aRow = lane & 15, aSel = (lane >> 4) * 16;
    const int bRow = lane & 7,  bSel = (lane >> 3) * 16;

    float acc[4][4][4];
    #pragma unroll
    for (int mt = 0; mt < 4; mt++)
        #pragma unroll
        for (int nt = 0; nt < 4; nt++)
            #pragma unroll
            for (int i = 0; i < 4; i++) acc[mt][nt][i] = 0.0f;

    // A-half of the prefetch (4 cp.async)
    auto load_A = [&](int c, int buf) {
        const uint32_t dA = sb + OFF_A + buf * TILE_B;
        const size_t koff = (size_t)c * BK * 2;
        #pragma unroll
        for (int p = 0; p < 4; p++) {
            const int row = ldr + p * 32;
            cp_async16(dA + row * SROW + ldg,
                       (const char*)g_vn + ((size_t)(m0 + row) * DIM) * 2 + koff + ldg);
        }
    };
    // B-half of the prefetch (4 cp.async) + group commit
    auto load_B = [&](int c, int buf) {
        const uint32_t dB = sb + OFF_B + buf * TILE_B;
        const size_t koff = (size_t)c * BK * 2;
        #pragma unroll
        for (int p = 0; p < 4; p++) {
            const int row = ldr + p * 32;
            cp_async16(dB + row * SROW + ldg,
                       (const char*)g_un + ((size_t)(n0 + row) * DIM) * 2 + koff + ldg);
        }
        cp_commit();
    };

    load_A(0, 0);
    load_B(0, 0);

    for (int c = 0; c < NCH; c++) {
        const int buf = c & 1;
        cp_wait<0>();        // group(c) is the only one outstanding -> landed
        __syncthreads();     // all warps done computing c-1; all see stage c

        const uint32_t bA = sb + OFF_A + buf * TILE_B;
        const uint32_t bB = sb + OFF_B + buf * TILE_B;
        const bool pf = (c + 1 < NCH);

        #pragma unroll
        for (int kp = 0; kp < 2; kp++) {
            const int kk = kp * 32;
            uint32_t bfr[4][4];
            #pragma unroll
            for (int nt = 0; nt < 4; nt++)
                ldmx4(bfr[nt], bB + (wn * 32 + nt * 8 + bRow) * SROW + kk * 2 + bSel);

            // ks = 0: fragments + MMAs, then sink 4 prefetch loads into the
            // tensor-dispatch shadow.
            {
                uint32_t af[4][4];
                #pragma unroll
                for (int mt = 0; mt < 4; mt++)
                    ldmx4(af[mt], bA + (wm * 64 + mt * 16 + aRow) * SROW + kk * 2 + aSel);
                #pragma unroll
                for (int mt = 0; mt < 4; mt++)
                    #pragma unroll
                    for (int nt = 0; nt < 4; nt++)
                        mma16816(acc[mt][nt], af[mt], bfr[nt][0], bfr[nt][1]);
            }
            if (pf) {
                if (kp == 0) load_A(c + 1, buf ^ 1);   // overwrites (c-1) slot
                else         load_B(c + 1, buf ^ 1);   // + commit
            }
            // ks = 1
            {
                const int kc = kk + 16;
                uint32_t af[4][4];
                #pragma unroll
                for (int mt = 0; mt < 4; mt++)
                    ldmx4(af[mt], bA + (wm * 64 + mt * 16 + aRow) * SROW + kc * 2 + aSel);
                #pragma unroll
                for (int mt = 0; mt < 4; mt++)
                    #pragma unroll
                    for (int nt = 0; nt < 4; nt++)
                        mma16816(acc[mt][nt], af[mt], bfr[nt][2], bfr[nt][3]);
            }
        }
    }

    // Epilogue: e = exp(cos*10 - 10); per-row / per-col partial sums.
    float rs0[4] = {0.f, 0.f, 0.f, 0.f};
    float rs1[4] = {0.f, 0.f, 0.f, 0.f};
    float ce[4]  = {0.f, 0.f, 0.f, 0.f};
    float co[4]  = {0.f, 0.f, 0.f, 0.f};
    #pragma unroll
    for (int mt = 0; mt < 4; mt++) {
        #pragma unroll
        for (int nt = 0; nt < 4; nt++) {
            float e0 = __expf(fmaf(acc[mt][nt][0], 10.0f, -10.0f));
            float e1 = __expf(fmaf(acc[mt][nt][1], 10.0f, -10.0f));
            float e2 = __expf(fmaf(acc[mt][nt][2], 10.0f, -10.0f));
            float e3 = __expf(fmaf(acc[mt][nt][3], 10.0f, -10.0f));
            rs0[mt] += e0 + e1;
            rs1[mt] += e2 + e3;
            ce[nt]  += e0 + e2;
            co[nt]  += e1 + e3;
        }
    }
    #pragma unroll
    for (int mt = 0; mt < 4; mt++) {
        float v0 = rs0[mt], v1 = rs1[mt];
        v0 += __shfl_xor_sync(0xFFFFFFFFu, v0, 1);
        v0 += __shfl_xor_sync(0xFFFFFFFFu, v0, 2);
        v1 += __shfl_xor_sync(0xFFFFFFFFu, v1, 1);
        v1 += __shfl_xor_sync(0xFFFFFFFFu, v1, 2);
        if (tid4 == 0) {
            atomicAdd(&s_row[wm * 64 + mt * 16 + gID], v0);
            atomicAdd(&s_row[wm * 64 + mt * 16 + gID + 8], v1);
        }
    }
    #pragma unroll
    for (int nt = 0; nt < 4; nt++) {
        float a = ce[nt], b = co[nt];
        a += __shfl_xor_sync(0xFFFFFFFFu, a, 4);
        a += __shfl_xor_sync(0xFFFFFFFFu, a, 8);
        a += __shfl_xor_sync(0xFFFFFFFFu, a, 16);
        b += __shfl_xor_sync(0xFFFFFFFFu, b, 4);
        b += __shfl_xor_sync(0xFFFFFFFFu, b, 8);
        b += __shfl_xor_sync(0xFFFFFFFFu, b, 16);
        if (lane < 4) {
            atomicAdd(&s_col[wn * 32 + nt * 8 + lane * 2], a);
            atomicAdd(&s_col[wn * 32 + nt * 8 + lane * 2 + 1], b);
        }
    }
    __syncthreads();
    if (tid < 128)       atomicAdd(&g_rowsum[m0 + tid], s_row[tid]);
    else                 atomicAdd(&g_colsum[n0 + tid - 128], s_col[tid - 128]);
}

// ---------------------------------------------------------------------------
// Kernel 3: finalize -> atomic accumulate of block partials into out[0]
// (out zeroed by normalize_kernel; same-stream ordering guarantees it).
// ---------------------------------------------------------------------------
__global__ void fin_kernel(float* __restrict__ out) {
    int i = blockIdx.x * 256 + threadIdx.x;
    float d10 = g_diag[i] * 10.0f;
    float li = logf(g_rowsum[i]) + 10.0f - d10;
    float lt = logf(g_colsum[i]) + 10.0f - d10;
    float s = 0.75f * li + 0.25f * lt;
    #pragma unroll
    for (int o = 16; o > 0; o >>= 1) s += __shfl_xor_sync(0xFFFFFFFFu, s, o);
    __shared__ float sh[8];
    int w = threadIdx.x >> 5, l = threadIdx.x & 31;
    if (l == 0) sh[w] = s;
    __syncthreads();
    if (threadIdx.x == 0) {
        float t = 0.f;
        #pragma unroll
        for (int i2 = 0; i2 < 8; i2++) t += sh[i2];
        atomicAdd(out, t * (1.0f / BSZ));
    }
}

extern "C" void kernel_launch(void* const* d_in, const int* in_sizes, int n_in,
                              void* d_out, int out_size) {
    const float* v = (const float*)d_in[0];
    const float* u = (const float*)d_in[1];
    float* out = (float*)d_out;

    static bool attr_set = false;
    if (!attr_set) {
        cudaFuncSetAttribute(gemm_lse_kernel,
                             cudaFuncAttributeMaxDynamicSharedMemorySize, SMEM_TOTAL);
        attr_set = true;
    }

    normalize_kernel<<<BSZ / 8, 256>>>(v, u, out);
    gemm_lse_kernel<<<dim3(64, 64), 256, SMEM_TOTAL>>>();
    fin_kernel<<<32, 256>>>(out);
}